// round 15
// baseline (speedup 1.0000x reference)
#include <cuda_runtime.h>
#include <cstdint>

#define HW   48000
#define NPTS 12000
#define KNN  16
#define ZPAGE (2u * HW)   // absolute index of the zeroed feature page

using ull = unsigned long long;

__device__ __forceinline__ ull pack2(float x, float y) {
    ull r; asm("mov.b64 %0, {%1, %2};" : "=l"(r) : "f"(x), "f"(y)); return r;
}
__device__ __forceinline__ float2 unpack2(ull v) {
    float2 r; asm("mov.b64 {%0, %1}, %2;" : "=f"(r.x), "=f"(r.y) : "l"(v)); return r;
}
__device__ __forceinline__ ull fma2(ull a, ull b, ull c) {
    ull d; asm("fma.rn.f32x2 %0, %1, %2, %3;" : "=l"(d) : "l"(a), "l"(b), "l"(c)); return d;
}
__device__ __forceinline__ ull mul2(ull a, ull b) {
    ull d; asm("mul.rn.f32x2 %0, %1, %2;" : "=l"(d) : "l"(a), "l"(b)); return d;
}
__device__ __forceinline__ ull add2(ull a, ull b) {
    ull d; asm("add.rn.f32x2 %0, %1, %2;" : "=l"(d) : "l"(a), "l"(b)); return d;
}
__device__ __forceinline__ void cp_async16(uint32_t dst_smem, const void* src) {
    asm volatile("cp.async.ca.shared.global [%0], [%1], 16;"
                 :: "r"(dst_smem), "l"(src) : "memory");
}
__device__ __forceinline__ void cp_commit() {
    asm volatile("cp.async.commit_group;" ::: "memory");
}
__device__ __forceinline__ void cp_wait0() {
    asm volatile("cp.async.wait_group 0;" ::: "memory");
}

// transposed feature map: [abs_pixel][64] + one zero page at ZPAGE
__device__ __align__(16) float g_ft[(2u * HW + 1u) * 64u];

// ---------------------------------------------------------------------------
// Kernel 1: f = leaky_relu(mlp_w @ features + mlp_b), transposed to [pix][c]
// 375 blocks x 256 threads; thread: 8 px x 8 ch.  (R8/R11/R13/R14-proven)
// ---------------------------------------------------------------------------
#define WS_PITCH 80
#define FT_PAD 264

__global__ void __launch_bounds__(256, 2) k_feat_mlp(
    const float* __restrict__ feat,   // [B,64,HW]
    const float* __restrict__ mw,     // [64,64] [cout][cin]
    const float* __restrict__ mb)     // [64]
{
    extern __shared__ float sm[];
    float* ws    = sm;                       // [64][WS_PITCH]
    float* ftile = ws + 64 * WS_PITCH;       // [8][FT_PAD]
    __shared__ float bsh[64];

    const int tid = threadIdx.x;
    for (int i = tid; i < 4096; i += 256) {
        int c = i >> 6, ci = i & 63;
        ws[ci * WS_PITCH + 10 * (c >> 3) + (c & 7)] = mw[i];
    }
    if (tid < 64) bsh[tid] = mb[tid];
    // keep the zero page zero (deterministic each launch)
    if (blockIdx.x == 0 && tid < 64) g_ft[(size_t)ZPAGE * 64 + tid] = 0.f;

    const long gpix0 = (long)blockIdx.x * 256;
    const long lpix = gpix0 + tid;
    const int lb = (lpix >= HW) ? 1 : 0;
    const float* fbase = feat + (size_t)lb * 64 * HW + (lpix - (long)lb * HW);

    float pre[8];
#pragma unroll
    for (int t = 0; t < 8; t++) pre[t] = fbase[(size_t)t * HW];
    __syncthreads();

    const int cg  = tid & 7;          // channel group (8 ch)
    const int pxg = tid >> 3;         // pixel group (8 px)

    ull acc[8][4];
#pragma unroll
    for (int p = 0; p < 8; p++)
#pragma unroll
        for (int q = 0; q < 4; q++)
            acc[p][q] = pack2(bsh[8 * cg + 2 * q], bsh[8 * cg + 2 * q + 1]);

    for (int chunk = 0; chunk < 8; chunk++) {
#pragma unroll
        for (int t = 0; t < 8; t++) ftile[t * FT_PAD + tid] = pre[t];
        __syncthreads();

        if (chunk < 7) {
#pragma unroll
            for (int t = 0; t < 8; t++)
                pre[t] = fbase[(size_t)((chunk + 1) * 8 + t) * HW];
        }

#pragma unroll
        for (int cc = 0; cc < 8; cc++) {
            const ull* wrow = reinterpret_cast<const ull*>(
                &ws[(chunk * 8 + cc) * WS_PITCH + 10 * cg]);
            ull wp[4];
#pragma unroll
            for (int q = 0; q < 4; q++) wp[q] = wrow[q];
            const float4 v0 = *reinterpret_cast<const float4*>(
                &ftile[cc * FT_PAD + 8 * pxg]);
            const float4 v1 = *reinterpret_cast<const float4*>(
                &ftile[cc * FT_PAD + 8 * pxg + 4]);
            const float vv[8] = {v0.x, v0.y, v0.z, v0.w, v1.x, v1.y, v1.z, v1.w};
#pragma unroll
            for (int p = 0; p < 8; p++) {
                const ull vp = pack2(vv[p], vv[p]);
#pragma unroll
                for (int q = 0; q < 4; q++)
                    acc[p][q] = fma2(wp[q], vp, acc[p][q]);
            }
        }
        __syncthreads();
    }

    // leaky relu + coalesced stores: per px, 2 STG.128 (8 ch)
    const size_t gbase = (size_t)gpix0 * 64;
#pragma unroll
    for (int p = 0; p < 8; p++) {
        const int px = 8 * pxg + p;
        float* dst = &g_ft[gbase + (size_t)px * 64 + 8 * cg];
        float2 t0 = unpack2(acc[p][0]);
        float2 t1 = unpack2(acc[p][1]);
        float2 t2 = unpack2(acc[p][2]);
        float2 t3 = unpack2(acc[p][3]);
        t0.x = (t0.x >= 0.f) ? t0.x : 0.1f * t0.x;
        t0.y = (t0.y >= 0.f) ? t0.y : 0.1f * t0.y;
        t1.x = (t1.x >= 0.f) ? t1.x : 0.1f * t1.x;
        t1.y = (t1.y >= 0.f) ? t1.y : 0.1f * t1.y;
        t2.x = (t2.x >= 0.f) ? t2.x : 0.1f * t2.x;
        t2.y = (t2.y >= 0.f) ? t2.y : 0.1f * t2.y;
        t3.x = (t3.x >= 0.f) ? t3.x : 0.1f * t3.x;
        t3.y = (t3.y >= 0.f) ? t3.y : 0.1f * t3.y;
        *reinterpret_cast<float4*>(dst)     = make_float4(t0.x, t0.y, t1.x, t1.y);
        *reinterpret_cast<float4*>(dst + 4) = make_float4(t2.x, t2.y, t3.x, t3.y);
    }
}

// ---------------------------------------------------------------------------
// Kernel 2 helpers: weight-net hidden layers; w2 matvec via LDS.128
// ---------------------------------------------------------------------------
__device__ __forceinline__ void phase1_h2(
    const float* s_w1, const float* s_b1, const float* s_b2,
    const float* w2base, int m0,
    float ox, float oy, float oz, float* dst_row)
{
    ull h1p[4];
#pragma unroll
    for (int rr = 0; rr < 4; rr++) {
        float t0 = s_b1[2 * rr] + s_w1[6 * rr] * ox
                 + s_w1[6 * rr + 1] * oy + s_w1[6 * rr + 2] * oz;
        float t1 = s_b1[2 * rr + 1] + s_w1[6 * rr + 3] * ox
                 + s_w1[6 * rr + 4] * oy + s_w1[6 * rr + 5] * oz;
        h1p[rr] = pack2(fmaxf(t0, 0.f), fmaxf(t1, 0.f));
    }
#pragma unroll
    for (int g4 = 0; g4 < 4; g4++) {
        float r[4];
#pragma unroll
        for (int kk = 0; kk < 4; kk++) {
            const int m = m0 + 4 * g4 + kk;
            const ulonglong2* wrow =
                reinterpret_cast<const ulonglong2*>(w2base + m * 8);
            const ulonglong2 w01 = wrow[0];
            const ulonglong2 w23 = wrow[1];
            ull a = mul2(w01.x, h1p[0]);
            a = fma2(w01.y, h1p[1], a);
            a = fma2(w23.x, h1p[2], a);
            a = fma2(w23.y, h1p[3], a);
            const float2 ra = unpack2(a);
            r[kk] = fmaxf(ra.x + ra.y + s_b2[m], 0.f);
        }
        *reinterpret_cast<float4*>(dst_row + m0 + 4 * g4) =
            make_float4(r[0], r[1], r[2], r[3]);
    }
}

// ---------------------------------------------------------------------------
// Kernel 2: gather + weight-net + f*wgt max over k.
// R14 pipeline, wave-balanced: grid = 740 blocks (exactly 5/SM x 148 = one
// co-resident wave); warps stride over 6000 four-point tiles.
// ---------------------------------------------------------------------------
#define NWARPS_TOT 2960          // 740 blocks x 4 warps
#define NTILES     6000          // 24000 points / 4 per tile

__global__ void __launch_bounds__(128, 5) k_gather(
    const float* __restrict__ xyz,    // [B,3,HW]
    const float* __restrict__ sxyz,   // [B,3,N]
    const int*   __restrict__ knn,    // [B,N,16]
    const int*   __restrict__ mask,   // [B,N,16] (bool widened to int32)
    const float* __restrict__ w1, const float* __restrict__ b1,
    const float* __restrict__ w2, const float* __restrict__ b2,
    const float* __restrict__ w3, const float* __restrict__ b3,
    float* __restrict__ out)          // [B,64,N]
{
    __shared__ float s_w1[24];
    __shared__ float s_b1[8];
    __shared__ __align__(16) float s_w2[520];   // copy0 @0, copy1 @260
    __shared__ float s_b2[32];
    __shared__ __align__(16) float s_h2[4][2][16][36];
    __shared__ int    s_idx[4][2][16];          // absolute zero-paged pixel idx
    __shared__ __align__(16) float2 s_fv[4][16][32];

    const int tid = threadIdx.x;
    const int w = tid >> 5, lane = tid & 31;

    if (tid < 24) s_w1[tid] = w1[tid];
    if (tid < 8)  s_b1[tid] = b1[tid];
    if (tid < 32) s_b2[tid] = b2[tid];
    { const int i = tid, i2 = tid + 128;
      s_w2[i] = w2[i];       s_w2[260 + i] = w2[i];
      s_w2[i2] = w2[i2];     s_w2[260 + i2] = w2[i2]; }

    const int c0 = 2 * lane;
    ull w3p0[16], w3p1[16];
    const ull* w3u = reinterpret_cast<const ull*>(w3);
#pragma unroll
    for (int e = 0; e < 16; e++) {
        w3p0[e] = w3u[c0 * 16 + e];
        w3p1[e] = w3u[(c0 + 1) * 16 + e];
    }
    const float b3c0 = b3[c0], b3c1 = b3[c0 + 1];
    __syncthreads();

    const int j = lane & 15, half = lane >> 4;
    const int m0 = half * 16;
    const float* w2base = s_w2 + (half ? 260 : 0);

    // 16B cp.async: lane l handles row 2i+half, channels 4*(l&15)..+3
    const int lane16 = lane & 15;
    const uint32_t fv_base16 =
        (uint32_t)__cvta_generic_to_shared(&s_fv[w][0][0])
        + (uint32_t)half * 256u + (uint32_t)lane16 * 16u;
    const float* gft_ch = g_ft + lane16 * 4;   // channel offset folded in

    const int gwarp = blockIdx.x * 4 + w;

    for (int tile = gwarp; tile < NTILES; tile += NWARPS_TOT) {
        const int b = (tile >= NTILES / 2) ? 1 : 0;
        const int n0 = tile * 4 - b * NPTS;

        const float* xyz_b = xyz + (size_t)b * 3 * HW;
        const float* sx_b  = sxyz + (size_t)b * 3 * NPTS;
        const unsigned bofs = (unsigned)b * HW;
        const long kb0 = ((long)b * NPTS + n0) * KNN + j;

        // pipeline registers (point pt+1)
        int pN, mN; float xN, yN, zN;

        // --- prologue: phase1(point 0) into buf0; prefetch point 1
        {
            const int p0 = knn[kb0];
            const int mv = (mask[kb0] != 0);
            const float kx = mv ? xyz_b[p0] : 0.f;
            const float ky = mv ? xyz_b[HW + p0] : 0.f;
            const float kz = mv ? xyz_b[2 * HW + p0] : 0.f;

            pN = knn[kb0 + KNN];
            mN = (mask[kb0 + KNN] != 0);
            xN = mN ? xyz_b[pN] : 0.f;
            yN = mN ? xyz_b[HW + pN] : 0.f;
            zN = mN ? xyz_b[2 * HW + pN] : 0.f;

            phase1_h2(s_w1, s_b1, s_b2, w2base, m0,
                      kx - sx_b[n0], ky - sx_b[NPTS + n0],
                      kz - sx_b[2 * NPTS + n0],
                      &s_h2[w][0][j][0]);
            if (half == 0)
                s_idx[w][0][j] = mv ? (int)(bofs + p0) : (int)ZPAGE;
        }
        __syncwarp();

        float ax[4], ay[4];
#pragma unroll
        for (int pt = 0; pt < 4; pt++) {
            const int cur = pt & 1, nxt = cur ^ 1;

            // ---- A: fv gathers, 16B per lane, 2 neighbor rows per instr
#pragma unroll
            for (int i = 0; i < 8; i++) {
                const int p = s_idx[w][cur][2 * i + half];
                cp_async16(fv_base16 + (uint32_t)i * 512u,
                           gft_ch + (size_t)p * 64);
            }
            cp_commit();

            // ---- B: phase1(pt+1) into other buffer; prefetch pt+2
            if (pt < 3) {
                const int n1 = n0 + pt + 1;
                const int pc = pN; const int mc = mN;
                const float xc = xN, yc = yN, zc = zN;
                if (pt < 2) {
                    const long kb2 = kb0 + (long)(pt + 2) * KNN;
                    pN = knn[kb2];
                    mN = (mask[kb2] != 0);
                    xN = mN ? xyz_b[pN] : 0.f;
                    yN = mN ? xyz_b[HW + pN] : 0.f;
                    zN = mN ? xyz_b[2 * HW + pN] : 0.f;
                }
                phase1_h2(s_w1, s_b1, s_b2, w2base, m0,
                          xc - sx_b[n1], yc - sx_b[NPTS + n1],
                          zc - sx_b[2 * NPTS + n1],
                          &s_h2[w][nxt][j][0]);
                if (half == 0)
                    s_idx[w][nxt][j] = mc ? (int)(bofs + pc) : (int)ZPAGE;
            }

            cp_wait0();

            // ---- D: phase2(pt): w3 layer + f*wgt, max over k
            float accx = -3.4e38f, accy = -3.4e38f;
#pragma unroll 4
            for (int jj = 0; jj < 16; jj += 2) {
                const float2 fA = s_fv[w][jj][lane];
                const float2 fB = s_fv[w][jj + 1][lane];
                const ulonglong2* hA =
                    reinterpret_cast<const ulonglong2*>(&s_h2[w][cur][jj][0]);
                const ulonglong2* hB =
                    reinterpret_cast<const ulonglong2*>(&s_h2[w][cur][jj + 1][0]);
                const ulonglong2 ha0 = hA[0];
                const ulonglong2 hb0 = hB[0];
                ull ax0 = mul2(w3p0[0], ha0.x), ax1 = mul2(w3p0[1], ha0.y);
                ull ay0 = mul2(w3p1[0], ha0.x), ay1 = mul2(w3p1[1], ha0.y);
                ull bx0 = mul2(w3p0[0], hb0.x), bx1 = mul2(w3p0[1], hb0.y);
                ull by0 = mul2(w3p1[0], hb0.x), by1 = mul2(w3p1[1], hb0.y);
#pragma unroll
                for (int e = 1; e < 8; e++) {
                    const ulonglong2 ha = hA[e];
                    const ulonglong2 hb = hB[e];
                    ax0 = fma2(w3p0[2 * e],     ha.x, ax0);
                    ax1 = fma2(w3p0[2 * e + 1], ha.y, ax1);
                    ay0 = fma2(w3p1[2 * e],     ha.x, ay0);
                    ay1 = fma2(w3p1[2 * e + 1], ha.y, ay1);
                    bx0 = fma2(w3p0[2 * e],     hb.x, bx0);
                    bx1 = fma2(w3p0[2 * e + 1], hb.y, bx1);
                    by0 = fma2(w3p1[2 * e],     hb.x, by0);
                    by1 = fma2(w3p1[2 * e + 1], hb.y, by1);
                }
                const float2 sax = unpack2(add2(ax0, ax1));
                const float2 say = unpack2(add2(ay0, ay1));
                const float2 sbx = unpack2(add2(bx0, bx1));
                const float2 sby = unpack2(add2(by0, by1));
                const float wgA0 = fmaxf(sax.x + sax.y + b3c0, 0.f);
                const float wgA1 = fmaxf(say.x + say.y + b3c1, 0.f);
                const float wgB0 = fmaxf(sbx.x + sbx.y + b3c0, 0.f);
                const float wgB1 = fmaxf(sby.x + sby.y + b3c1, 0.f);
                accx = fmaxf(accx, fA.x * wgA0);
                accy = fmaxf(accy, fA.y * wgA1);
                accx = fmaxf(accx, fB.x * wgB0);
                accy = fmaxf(accy, fB.y * wgB1);
            }
            ax[pt] = accx;
            ay[pt] = accy;
            __syncwarp();
        }

        // ---- flush 4 points per channel as STG.128
        float* outb = out + (size_t)b * 64 * NPTS + n0;
        *reinterpret_cast<float4*>(outb + (size_t)c0 * NPTS) =
            make_float4(ax[0], ax[1], ax[2], ax[3]);
        *reinterpret_cast<float4*>(outb + (size_t)(c0 + 1) * NPTS) =
            make_float4(ay[0], ay[1], ay[2], ay[3]);
    }
}

extern "C" void kernel_launch(void* const* d_in, const int* in_sizes, int n_in,
                              void* d_out, int out_size)
{
    const float* xyz  = (const float*)d_in[0];
    const float* feat = (const float*)d_in[1];
    const float* sx   = (const float*)d_in[2];
    const int*   knn  = (const int*)d_in[3];
    const int*   mask = (const int*)d_in[4];
    const float* mw = (const float*)d_in[5];
    const float* mb = (const float*)d_in[6];
    const float* w1 = (const float*)d_in[7];
    const float* b1 = (const float*)d_in[8];
    const float* w2 = (const float*)d_in[9];
    const float* b2 = (const float*)d_in[10];
    const float* w3 = (const float*)d_in[11];
    const float* b3 = (const float*)d_in[12];
    float* out = (float*)d_out;

    const int k1_smem = (64 * WS_PITCH + 8 * FT_PAD) * sizeof(float);
    k_feat_mlp<<<375, 256, k1_smem>>>(feat, mw, mb);
    k_gather<<<740, 128>>>(xyz, sx, knn, mask, w1, b1, w2, b2, w3, b3, out);
}

// round 16
// speedup vs baseline: 1.0899x; 1.0899x over previous
#include <cuda_runtime.h>
#include <cstdint>

#define HW   48000
#define NPTS 12000
#define KNN  16
#define ZPAGE (2u * HW)   // absolute index of the zeroed feature page

using ull = unsigned long long;

__device__ __forceinline__ ull pack2(float x, float y) {
    ull r; asm("mov.b64 %0, {%1, %2};" : "=l"(r) : "f"(x), "f"(y)); return r;
}
__device__ __forceinline__ float2 unpack2(ull v) {
    float2 r; asm("mov.b64 {%0, %1}, %2;" : "=f"(r.x), "=f"(r.y) : "l"(v)); return r;
}
__device__ __forceinline__ ull fma2(ull a, ull b, ull c) {
    ull d; asm("fma.rn.f32x2 %0, %1, %2, %3;" : "=l"(d) : "l"(a), "l"(b), "l"(c)); return d;
}
__device__ __forceinline__ ull mul2(ull a, ull b) {
    ull d; asm("mul.rn.f32x2 %0, %1, %2;" : "=l"(d) : "l"(a), "l"(b)); return d;
}
__device__ __forceinline__ ull add2(ull a, ull b) {
    ull d; asm("add.rn.f32x2 %0, %1, %2;" : "=l"(d) : "l"(a), "l"(b)); return d;
}
__device__ __forceinline__ void cp_async16(uint32_t dst_smem, const void* src) {
    asm volatile("cp.async.ca.shared.global [%0], [%1], 16;"
                 :: "r"(dst_smem), "l"(src) : "memory");
}
__device__ __forceinline__ void cp_commit() {
    asm volatile("cp.async.commit_group;" ::: "memory");
}
__device__ __forceinline__ void cp_wait0() {
    asm volatile("cp.async.wait_group 0;" ::: "memory");
}

// transposed feature map: [abs_pixel][64] + one zero page at ZPAGE
__device__ __align__(16) float g_ft[(2u * HW + 1u) * 64u];

// ---------------------------------------------------------------------------
// Kernel 1: f = leaky_relu(mlp_w @ features + mlp_b), transposed to [pix][c]
// 750 blocks x 128 threads; thread: 8 px x 8 ch (proven ratio), 128-px tiles.
// Single co-resident wave at 5 blocks/SM.
// ---------------------------------------------------------------------------
#define WS_PITCH 80
#define FT_PAD 136

__global__ void __launch_bounds__(128, 5) k_feat_mlp(
    const float* __restrict__ feat,   // [B,64,HW]
    const float* __restrict__ mw,     // [64,64] [cout][cin]
    const float* __restrict__ mb)     // [64]
{
    extern __shared__ float sm[];
    float* ws    = sm;                       // [64][WS_PITCH]
    float* ftile = ws + 64 * WS_PITCH;       // [8][FT_PAD]
    __shared__ float bsh[64];

    const int tid = threadIdx.x;
    for (int i = tid; i < 4096; i += 128) {
        int c = i >> 6, ci = i & 63;
        ws[ci * WS_PITCH + 10 * (c >> 3) + (c & 7)] = mw[i];
    }
    if (tid < 64) bsh[tid] = mb[tid];
    // keep the zero page zero (deterministic each launch)
    if (blockIdx.x == 0 && tid < 64) g_ft[(size_t)ZPAGE * 64 + tid] = 0.f;

    const long gpix0 = (long)blockIdx.x * 128;
    const long lpix = gpix0 + tid;
    const int lb = (lpix >= HW) ? 1 : 0;
    const float* fbase = feat + (size_t)lb * 64 * HW + (lpix - (long)lb * HW);

    float pre[8];
#pragma unroll
    for (int t = 0; t < 8; t++) pre[t] = fbase[(size_t)t * HW];
    __syncthreads();

    const int cg  = tid & 7;          // channel group (8 ch)
    const int pxg = tid >> 3;         // pixel group (8 px), 0..15

    ull acc[8][4];
#pragma unroll
    for (int p = 0; p < 8; p++)
#pragma unroll
        for (int q = 0; q < 4; q++)
            acc[p][q] = pack2(bsh[8 * cg + 2 * q], bsh[8 * cg + 2 * q + 1]);

    for (int chunk = 0; chunk < 8; chunk++) {
#pragma unroll
        for (int t = 0; t < 8; t++) ftile[t * FT_PAD + tid] = pre[t];
        __syncthreads();

        if (chunk < 7) {
#pragma unroll
            for (int t = 0; t < 8; t++)
                pre[t] = fbase[(size_t)((chunk + 1) * 8 + t) * HW];
        }

#pragma unroll
        for (int cc = 0; cc < 8; cc++) {
            const ull* wrow = reinterpret_cast<const ull*>(
                &ws[(chunk * 8 + cc) * WS_PITCH + 10 * cg]);
            ull wp[4];
#pragma unroll
            for (int q = 0; q < 4; q++) wp[q] = wrow[q];
            const float4 v0 = *reinterpret_cast<const float4*>(
                &ftile[cc * FT_PAD + 8 * pxg]);
            const float4 v1 = *reinterpret_cast<const float4*>(
                &ftile[cc * FT_PAD + 8 * pxg + 4]);
            const float vv[8] = {v0.x, v0.y, v0.z, v0.w, v1.x, v1.y, v1.z, v1.w};
#pragma unroll
            for (int p = 0; p < 8; p++) {
                const ull vp = pack2(vv[p], vv[p]);
#pragma unroll
                for (int q = 0; q < 4; q++)
                    acc[p][q] = fma2(wp[q], vp, acc[p][q]);
            }
        }
        __syncthreads();
    }

    // leaky relu + coalesced stores: per px, 2 STG.128 (8 ch)
    const size_t gbase = (size_t)gpix0 * 64;
#pragma unroll
    for (int p = 0; p < 8; p++) {
        const int px = 8 * pxg + p;
        float* dst = &g_ft[gbase + (size_t)px * 64 + 8 * cg];
        float2 t0 = unpack2(acc[p][0]);
        float2 t1 = unpack2(acc[p][1]);
        float2 t2 = unpack2(acc[p][2]);
        float2 t3 = unpack2(acc[p][3]);
        t0.x = (t0.x >= 0.f) ? t0.x : 0.1f * t0.x;
        t0.y = (t0.y >= 0.f) ? t0.y : 0.1f * t0.y;
        t1.x = (t1.x >= 0.f) ? t1.x : 0.1f * t1.x;
        t1.y = (t1.y >= 0.f) ? t1.y : 0.1f * t1.y;
        t2.x = (t2.x >= 0.f) ? t2.x : 0.1f * t2.x;
        t2.y = (t2.y >= 0.f) ? t2.y : 0.1f * t2.y;
        t3.x = (t3.x >= 0.f) ? t3.x : 0.1f * t3.x;
        t3.y = (t3.y >= 0.f) ? t3.y : 0.1f * t3.y;
        *reinterpret_cast<float4*>(dst)     = make_float4(t0.x, t0.y, t1.x, t1.y);
        *reinterpret_cast<float4*>(dst + 4) = make_float4(t2.x, t2.y, t3.x, t3.y);
    }
}

// ---------------------------------------------------------------------------
// Kernel 2 helpers: weight-net hidden layers; w2 matvec via LDS.128
// ---------------------------------------------------------------------------
__device__ __forceinline__ void phase1_h2(
    const float* s_w1, const float* s_b1, const float* s_b2,
    const float* w2base, int m0,
    float ox, float oy, float oz, float* dst_row)
{
    ull h1p[4];
#pragma unroll
    for (int rr = 0; rr < 4; rr++) {
        float t0 = s_b1[2 * rr] + s_w1[6 * rr] * ox
                 + s_w1[6 * rr + 1] * oy + s_w1[6 * rr + 2] * oz;
        float t1 = s_b1[2 * rr + 1] + s_w1[6 * rr + 3] * ox
                 + s_w1[6 * rr + 4] * oy + s_w1[6 * rr + 5] * oz;
        h1p[rr] = pack2(fmaxf(t0, 0.f), fmaxf(t1, 0.f));
    }
#pragma unroll
    for (int g4 = 0; g4 < 4; g4++) {
        float r[4];
#pragma unroll
        for (int kk = 0; kk < 4; kk++) {
            const int m = m0 + 4 * g4 + kk;
            const ulonglong2* wrow =
                reinterpret_cast<const ulonglong2*>(w2base + m * 8);
            const ulonglong2 w01 = wrow[0];
            const ulonglong2 w23 = wrow[1];
            ull a = mul2(w01.x, h1p[0]);
            a = fma2(w01.y, h1p[1], a);
            a = fma2(w23.x, h1p[2], a);
            a = fma2(w23.y, h1p[3], a);
            const float2 ra = unpack2(a);
            r[kk] = fmaxf(ra.x + ra.y + s_b2[m], 0.f);
        }
        *reinterpret_cast<float4*>(dst_row + m0 + 4 * g4) =
            make_float4(r[0], r[1], r[2], r[3]);
    }
}

// ---------------------------------------------------------------------------
// Kernel 2: gather + weight-net + f*wgt max over k.  (R14-proven, 77.1us)
// 750 blocks x 128 threads = 4 independent warps; warp = 8 points, 2 ch/lane;
// 16B cp.async fv gathers; output register-staged over 4 points.
// ---------------------------------------------------------------------------
__global__ void __launch_bounds__(128, 5) k_gather(
    const float* __restrict__ xyz,    // [B,3,HW]
    const float* __restrict__ sxyz,   // [B,3,N]
    const int*   __restrict__ knn,    // [B,N,16]
    const int*   __restrict__ mask,   // [B,N,16] (bool widened to int32)
    const float* __restrict__ w1, const float* __restrict__ b1,
    const float* __restrict__ w2, const float* __restrict__ b2,
    const float* __restrict__ w3, const float* __restrict__ b3,
    float* __restrict__ out)          // [B,64,N]
{
    __shared__ float s_w1[24];
    __shared__ float s_b1[8];
    __shared__ __align__(16) float s_w2[520];   // copy0 @0, copy1 @260
    __shared__ float s_b2[32];
    __shared__ __align__(16) float s_h2[4][2][16][36];
    __shared__ int    s_idx[4][2][16];          // absolute zero-paged pixel idx
    __shared__ __align__(16) float2 s_fv[4][16][32];

    const int tid = threadIdx.x;
    const int w = tid >> 5, lane = tid & 31;

    if (tid < 24) s_w1[tid] = w1[tid];
    if (tid < 8)  s_b1[tid] = b1[tid];
    if (tid < 32) s_b2[tid] = b2[tid];
    { const int i = tid, i2 = tid + 128;
      s_w2[i] = w2[i];       s_w2[260 + i] = w2[i];
      s_w2[i2] = w2[i2];     s_w2[260 + i2] = w2[i2]; }

    const int c0 = 2 * lane;
    ull w3p0[16], w3p1[16];
    const ull* w3u = reinterpret_cast<const ull*>(w3);
#pragma unroll
    for (int e = 0; e < 16; e++) {
        w3p0[e] = w3u[c0 * 16 + e];
        w3p1[e] = w3u[(c0 + 1) * 16 + e];
    }
    const float b3c0 = b3[c0], b3c1 = b3[c0 + 1];
    __syncthreads();

    const int b = blockIdx.x / 375;
    const int n_block = (blockIdx.x % 375) * 32;

    const float* xyz_b = xyz + (size_t)b * 3 * HW;
    const float* sx_b  = sxyz + (size_t)b * 3 * NPTS;
    const unsigned bofs = (unsigned)b * HW;

    const int j = lane & 15, half = lane >> 4;
    const int m0 = half * 16;
    const float* w2base = s_w2 + (half ? 260 : 0);
    const int n0 = n_block + w * 8;
    const long kb0 = ((long)b * NPTS + n0) * KNN + j;

    // 16B cp.async: lane l handles row 2i+half, channels 4*(l&15)..+3
    const int lane16 = lane & 15;
    const uint32_t fv_base16 =
        (uint32_t)__cvta_generic_to_shared(&s_fv[w][0][0])
        + (uint32_t)half * 256u + (uint32_t)lane16 * 16u;
    const float* gft_ch = g_ft + lane16 * 4;   // channel offset folded in

    // pipeline registers (point pt+1)
    int pN, mN; float xN, yN, zN;

    // --- prologue: phase1(point 0) into buf0; prefetch point 1
    {
        const int p0 = knn[kb0];
        const int mv = (mask[kb0] != 0);
        const float kx = mv ? xyz_b[p0] : 0.f;
        const float ky = mv ? xyz_b[HW + p0] : 0.f;
        const float kz = mv ? xyz_b[2 * HW + p0] : 0.f;

        pN = knn[kb0 + KNN];
        mN = (mask[kb0 + KNN] != 0);
        xN = mN ? xyz_b[pN] : 0.f;
        yN = mN ? xyz_b[HW + pN] : 0.f;
        zN = mN ? xyz_b[2 * HW + pN] : 0.f;

        phase1_h2(s_w1, s_b1, s_b2, w2base, m0,
                  kx - sx_b[n0], ky - sx_b[NPTS + n0], kz - sx_b[2 * NPTS + n0],
                  &s_h2[w][0][j][0]);
        if (half == 0)
            s_idx[w][0][j] = mv ? (int)(bofs + p0) : (int)ZPAGE;
    }
    __syncwarp();

    float* outb = out + (size_t)b * 64 * NPTS + n0;

    for (int pt4 = 0; pt4 < 8; pt4 += 4) {
        float ax[4], ay[4];
#pragma unroll
        for (int q = 0; q < 4; q++) {
            const int pt = pt4 + q;
            const int cur = pt & 1, nxt = cur ^ 1;

            // ---- A: fv gathers, 16B per lane, 2 neighbor rows per instr
#pragma unroll
            for (int i = 0; i < 8; i++) {
                const int p = s_idx[w][cur][2 * i + half];
                cp_async16(fv_base16 + (uint32_t)i * 512u,
                           gft_ch + (size_t)p * 64);
            }
            cp_commit();

            // ---- B: phase1(pt+1) into other buffer; prefetch pt+2
            if (pt < 7) {
                const int n1 = n0 + pt + 1;
                const int pc = pN; const int mc = mN;
                const float xc = xN, yc = yN, zc = zN;
                if (pt < 6) {
                    const long kb2 = kb0 + (long)(pt + 2) * KNN;
                    pN = knn[kb2];
                    mN = (mask[kb2] != 0);
                    xN = mN ? xyz_b[pN] : 0.f;
                    yN = mN ? xyz_b[HW + pN] : 0.f;
                    zN = mN ? xyz_b[2 * HW + pN] : 0.f;
                }
                phase1_h2(s_w1, s_b1, s_b2, w2base, m0,
                          xc - sx_b[n1], yc - sx_b[NPTS + n1],
                          zc - sx_b[2 * NPTS + n1],
                          &s_h2[w][nxt][j][0]);
                if (half == 0)
                    s_idx[w][nxt][j] = mc ? (int)(bofs + pc) : (int)ZPAGE;
            }

            cp_wait0();

            // ---- D: phase2(pt): w3 layer + f*wgt, max over k
            float accx = -3.4e38f, accy = -3.4e38f;
#pragma unroll 4
            for (int jj = 0; jj < 16; jj += 2) {
                const float2 fA = s_fv[w][jj][lane];
                const float2 fB = s_fv[w][jj + 1][lane];
                const ulonglong2* hA =
                    reinterpret_cast<const ulonglong2*>(&s_h2[w][cur][jj][0]);
                const ulonglong2* hB =
                    reinterpret_cast<const ulonglong2*>(&s_h2[w][cur][jj + 1][0]);
                const ulonglong2 ha0 = hA[0];
                const ulonglong2 hb0 = hB[0];
                ull ax0 = mul2(w3p0[0], ha0.x), ax1 = mul2(w3p0[1], ha0.y);
                ull ay0 = mul2(w3p1[0], ha0.x), ay1 = mul2(w3p1[1], ha0.y);
                ull bx0 = mul2(w3p0[0], hb0.x), bx1 = mul2(w3p0[1], hb0.y);
                ull by0 = mul2(w3p1[0], hb0.x), by1 = mul2(w3p1[1], hb0.y);
#pragma unroll
                for (int e = 1; e < 8; e++) {
                    const ulonglong2 ha = hA[e];
                    const ulonglong2 hb = hB[e];
                    ax0 = fma2(w3p0[2 * e],     ha.x, ax0);
                    ax1 = fma2(w3p0[2 * e + 1], ha.y, ax1);
                    ay0 = fma2(w3p1[2 * e],     ha.x, ay0);
                    ay1 = fma2(w3p1[2 * e + 1], ha.y, ay1);
                    bx0 = fma2(w3p0[2 * e],     hb.x, bx0);
                    bx1 = fma2(w3p0[2 * e + 1], hb.y, bx1);
                    by0 = fma2(w3p1[2 * e],     hb.x, by0);
                    by1 = fma2(w3p1[2 * e + 1], hb.y, by1);
                }
                const float2 sax = unpack2(add2(ax0, ax1));
                const float2 say = unpack2(add2(ay0, ay1));
                const float2 sbx = unpack2(add2(bx0, bx1));
                const float2 sby = unpack2(add2(by0, by1));
                const float wgA0 = fmaxf(sax.x + sax.y + b3c0, 0.f);
                const float wgA1 = fmaxf(say.x + say.y + b3c1, 0.f);
                const float wgB0 = fmaxf(sbx.x + sbx.y + b3c0, 0.f);
                const float wgB1 = fmaxf(sby.x + sby.y + b3c1, 0.f);
                accx = fmaxf(accx, fA.x * wgA0);
                accy = fmaxf(accy, fA.y * wgA1);
                accx = fmaxf(accx, fB.x * wgB0);
                accy = fmaxf(accy, fB.y * wgB1);
            }
            ax[q] = accx;
            ay[q] = accy;
            __syncwarp();
        }
        // ---- flush 4 points per channel as STG.128
        *reinterpret_cast<float4*>(outb + (size_t)c0 * NPTS + pt4) =
            make_float4(ax[0], ax[1], ax[2], ax[3]);
        *reinterpret_cast<float4*>(outb + (size_t)(c0 + 1) * NPTS + pt4) =
            make_float4(ay[0], ay[1], ay[2], ay[3]);
    }
}

extern "C" void kernel_launch(void* const* d_in, const int* in_sizes, int n_in,
                              void* d_out, int out_size)
{
    const float* xyz  = (const float*)d_in[0];
    const float* feat = (const float*)d_in[1];
    const float* sx   = (const float*)d_in[2];
    const int*   knn  = (const int*)d_in[3];
    const int*   mask = (const int*)d_in[4];
    const float* mw = (const float*)d_in[5];
    const float* mb = (const float*)d_in[6];
    const float* w1 = (const float*)d_in[7];
    const float* b1 = (const float*)d_in[8];
    const float* w2 = (const float*)d_in[9];
    const float* b2 = (const float*)d_in[10];
    const float* w3 = (const float*)d_in[11];
    const float* b3 = (const float*)d_in[12];
    float* out = (float*)d_out;

    const int k1_smem = (64 * WS_PITCH + 8 * FT_PAD) * sizeof(float);
    k_feat_mlp<<<750, 128, k1_smem>>>(feat, mw, mb);
    k_gather<<<750, 128>>>(xyz, sx, knn, mask, w1, b1, w2, b2, w3, b3, out);
}